// round 4
// baseline (speedup 1.0000x reference)
#include <cuda_runtime.h>
#include <math.h>

// ---------------- problem constants ----------------
#define BATCH   64
#define CIN     32
#define T_IN    2048
#define F       64
#define WIN     5
#define TPOOL   2040            // after conv(valid)+maxpool5
#define L       2036            // after conv2
#define D       256
#define DA      64
#define SECTORS 11
#define ATT_SIZE (BATCH*L)

// conv1 tiling: 512 threads = 64 filters x 8 groups, 13 pooled / 17 conv / 21 x per group
#define GROUPS    8
#define POOL_PER_G 13
#define CONV_PER_G 17
#define XS_W      112
#define TILE_P    (GROUPS*POOL_PER_G)   // 104
#define NTILE     20                    // 20*104 = 2080 >= 2040
#define NBLK1     (BATCH*NTILE)         // 1280

// ---------------- device scratch (static: no allocations allowed) ----------
__device__ float  g_wT[CIN*WIN*F];        // conv1 weights as [c][k][f]
__device__ float  g_W1T[L*DA];            // W1 transposed: [l][a]
__device__ float  g_hp[BATCH*TPOOL*F];    // pooled conv1 output (fp32), layout [b][p][f]
__device__ double g_psumd[NBLK1*F];
__device__ double g_psqd [NBLK1*F];
__device__ float  g_muf[F];               // fp32-rounded exact mean
__device__ float  g_rf [F];               // fp32-rounded exact rsqrt(fl(var)+1e-5f)
__device__ int    g_idx[BATCH*L];         // quantization bucket per (b,l), in [0,255]
__device__ float  g_Apart[4*BATCH*D];     // partial A over a-chunks
__device__ float  g_P[BATCH*D];           // P[b][j] = emb[j,:] . A[b,:]

// ---------------- K0: weight reshapes -------------------------------------
__global__ void k0_prep(const float* __restrict__ conv1_w,
                        const float* __restrict__ W1) {
    int i = blockIdx.x * blockDim.x + threadIdx.x;
    int stride = gridDim.x * blockDim.x;
    for (int j = i; j < CIN*WIN*F; j += stride) {
        int f = j % F;
        int ck = j / F;
        int k = ck % WIN;
        int c = ck / WIN;
        g_wT[j] = conv1_w[(f*CIN + c)*WIN + k];
    }
    for (int j = i; j < L*DA; j += stride) {
        int a = j % DA;
        int l = j / DA;
        g_W1T[j] = W1[a*L + l];
    }
}

// ---------------- K1: conv1 (double-accum) + maxpool5 + BN partials --------
// grid (NTILE, BATCH), 512 threads = 64 filters x 8 t-groups.
// Per channel: fp32 5-tap fma chain (err ~2e-8), DADD into double accumulator
// (fp64 pipe, hidden under FFMA issue). h rounded once to fp32.
__global__ __launch_bounds__(512) void k1_conv1(const float* __restrict__ x,
                                                const float* __restrict__ conv1_b) {
    __shared__ float  xs[CIN][XS_W];
    __shared__ double s_part[2][GROUPS][F];
    const int b    = blockIdx.y;
    const int tile = blockIdx.x;
    const int p0   = tile * TILE_P;
    const int tid  = threadIdx.x;

    const float* xb = x + (size_t)b * CIN * T_IN;
    for (int i = tid; i < CIN*XS_W; i += 512) {
        int c = i / XS_W, t = i - c*XS_W;
        int gt = p0 + t;
        if (gt > T_IN-1) gt = T_IN-1;        // clamped values never feed valid outputs
        xs[c][t] = xb[c*T_IN + gt];
    }
    __syncthreads();

    const int f    = tid & 63;
    const int g    = tid >> 6;
    const int base = g * POOL_PER_G;

    double acc[CONV_PER_G];
    {
        double bias = (double)conv1_b[f];
        #pragma unroll
        for (int t = 0; t < CONV_PER_G; t++) acc[t] = bias;
    }

    for (int c = 0; c < CIN; c++) {
        float wv[WIN];
        #pragma unroll
        for (int k = 0; k < WIN; k++) wv[k] = __ldg(&g_wT[(c*WIN + k)*F + f]);
        float xv[CONV_PER_G + WIN - 1];
        #pragma unroll
        for (int t = 0; t < CONV_PER_G + WIN - 1; t++) xv[t] = xs[c][base + t];
        #pragma unroll
        for (int t = 0; t < CONV_PER_G; t++) {
            float cacc = __fmul_rn(xv[t], wv[0]);
            cacc = fmaf(xv[t+1], wv[1], cacc);
            cacc = fmaf(xv[t+2], wv[2], cacc);
            cacc = fmaf(xv[t+3], wv[3], cacc);
            cacc = fmaf(xv[t+4], wv[4], cacc);
            acc[t] += (double)cacc;
        }
    }

    // round once to fp32 (monotone: commutes with the max-pool)
    float hc[CONV_PER_G];
    #pragma unroll
    for (int t = 0; t < CONV_PER_G; t++) hc[t] = (float)acc[t];

    // maxpool(5, stride 1) thread-local; store [b][p][f] (coalesced)
    double s = 0.0, sq = 0.0;
    float* hpb = g_hp + (size_t)b * TPOOL * F;
    #pragma unroll
    for (int t = 0; t < POOL_PER_G; t++) {
        float m = hc[t];
        m = fmaxf(m, hc[t+1]); m = fmaxf(m, hc[t+2]);
        m = fmaxf(m, hc[t+3]); m = fmaxf(m, hc[t+4]);
        int p = p0 + base + t;
        if (p < TPOOL) {
            hpb[p*F + f] = m;
            s  += (double)m;
            sq += (double)m * (double)m;
        }
    }
    s_part[0][g][f] = s;
    s_part[1][g][f] = sq;
    __syncthreads();
    if (g == 0) {   // deterministic fixed-order combine
        double ts = 0.0, tq = 0.0;
        #pragma unroll
        for (int gg = 0; gg < GROUPS; gg++) { ts += s_part[0][gg][f]; tq += s_part[1][gg][f]; }
        int blk = b*NTILE + tile;
        g_psumd[blk*F + f] = ts;
        g_psqd [blk*F + f] = tq;
    }
}

// ---------------- K2: exact BN reduce -> fp32 mu and rsqrt ------------------
__global__ void k2_bn(void) {
    __shared__ double red[256];
    const int f = blockIdx.x, tid = threadIdx.x;
    double s = 0.0;
    for (int i = tid; i < NBLK1; i += 256) s += g_psumd[i*F + f];
    red[tid] = s; __syncthreads();
    for (int st = 128; st > 0; st >>= 1) { if (tid < st) red[tid] += red[tid+st]; __syncthreads(); }
    double tot = red[0]; __syncthreads();
    double q = 0.0;
    for (int i = tid; i < NBLK1; i += 256) q += g_psqd[i*F + f];
    red[tid] = q; __syncthreads();
    for (int st = 128; st > 0; st >>= 1) { if (tid < st) red[tid] += red[tid+st]; __syncthreads(); }
    if (tid == 0) {
        const double cnt = (double)BATCH * TPOOL;
        double mu  = tot / cnt;
        double var = red[0] / cnt - mu*mu;
        float muf  = (float)mu;
        float varf = (float)var;                        // ref's var is an fp32 value
        float sf   = __fadd_rn(varf, 1e-5f);            // ref: var + BN_EPS in fp32
        double r   = 1.0 / sqrt((double)sf);            // correctly-rounded rsqrt
        g_muf[f] = muf;
        g_rf [f] = (float)r;
    }
}

// ---------------- K4: fp32 BN steps + conv2 (double) + sigmoid -> idx -------
// grid (16, BATCH), 256 threads; tile of 128 l.
// BN applied at tile load with the reference's exact fp32 step order (no fma
// contraction): t4 = (((h - mu) * r) * gamma) + beta.
__global__ __launch_bounds__(256) void k4_conv2(const float* __restrict__ bn_gamma,
                                                const float* __restrict__ bn_beta,
                                                const float* __restrict__ conv2_w,
                                                const float* __restrict__ conv2_b) {
    __shared__ float  hps[132*65];       // padded stride 65 -> conflict-free
    __shared__ float  w2s[F*WIN];
    __shared__ double part2[2][128];
    const int b  = blockIdx.y;
    const int l0 = blockIdx.x * 128;
    const int tid = threadIdx.x;

    const float* hpb = g_hp + (size_t)b * TPOOL * F;
    for (int i = tid; i < 132*F; i += 256) {
        int p = i >> 6, f = i & 63;
        int gp = l0 + p;
        if (gp > TPOOL-1) gp = TPOOL-1;               // feeds only discarded l
        float h  = hpb[gp*F + f];
        float t1 = __fsub_rn(h,  g_muf[f]);
        float t2 = __fmul_rn(t1, g_rf[f]);
        float t3 = __fmul_rn(t2, bn_gamma[f]);
        float t4 = __fadd_rn(t3, bn_beta[f]);
        hps[p*65 + f] = t4;
    }
    for (int i = tid; i < F*WIN; i += 256) w2s[i] = conv2_w[i];
    __syncthreads();

    const int half = tid >> 7, lloc = tid & 127;
    const int f0 = half * 32;
    double vacc = 0.0;
    for (int f = f0; f < f0 + 32; f++) {
        double w0 = (double)w2s[f*WIN+0], w1 = (double)w2s[f*WIN+1];
        double w2v = (double)w2s[f*WIN+2];
        double w3 = (double)w2s[f*WIN+3], w4 = (double)w2s[f*WIN+4];
        vacc = fma((double)hps[(lloc  )*65 + f], w0, vacc);
        vacc = fma((double)hps[(lloc+1)*65 + f], w1, vacc);
        vacc = fma((double)hps[(lloc+2)*65 + f], w2v, vacc);
        vacc = fma((double)hps[(lloc+3)*65 + f], w3, vacc);
        vacc = fma((double)hps[(lloc+4)*65 + f], w4, vacc);
    }
    part2[half][lloc] = vacc;
    __syncthreads();
    if (half == 0) {
        int l = l0 + lloc;
        if (l < L) {
            double vd = part2[0][lloc] + part2[1][lloc] + (double)conv2_b[0];
            float vf = (float)vd;                     // ref conv2 output is fp32
            vf = fmaxf(vf, 0.f);                      // relu (fp32, exact)
            double cd = 1.0 / (1.0 + exp(-(double)vf)); // true sigmoid of fp32 v
            float cf = (float)cd;                     // round c to fp32 like ref
            float pf = __fmul_rn(cf, 256.0f);         // exact (x2^8)
            int id = (int)ceilf(pf) - 1;
            id = min(max(id, 0), 255);
            g_idx[b*L + l] = id;
        }
    }
}

// ---------------- K5: bucket scatter + tau = S@E + tanh + partial A --------
// grid (4 a-chunks, BATCH), 256 threads. S in shared (16 x 260 padded).
__global__ __launch_bounds__(256) void k5_att(const float* __restrict__ emb,
                                              const float* __restrict__ W2) {
    __shared__ float S[16*260];   // stride 260: float4-aligned, banks spread
    const int b = blockIdx.y, chunk = blockIdx.x;
    const int a0 = chunk * 16;
    const int tid = threadIdx.x;

    for (int i = tid; i < 16*260; i += 256) S[i] = 0.f;
    __syncthreads();

    const int* idxb = g_idx + b*L;
    for (int l = tid; l < L; l += 256) {
        int j = idxb[l];
        const float4* w4 = (const float4*)(g_W1T + l*DA + a0);
        float4 v0 = w4[0], v1 = w4[1], v2 = w4[2], v3 = w4[3];
        atomicAdd(&S[ 0*260 + j], v0.x); atomicAdd(&S[ 1*260 + j], v0.y);
        atomicAdd(&S[ 2*260 + j], v0.z); atomicAdd(&S[ 3*260 + j], v0.w);
        atomicAdd(&S[ 4*260 + j], v1.x); atomicAdd(&S[ 5*260 + j], v1.y);
        atomicAdd(&S[ 6*260 + j], v1.z); atomicAdd(&S[ 7*260 + j], v1.w);
        atomicAdd(&S[ 8*260 + j], v2.x); atomicAdd(&S[ 9*260 + j], v2.y);
        atomicAdd(&S[10*260 + j], v2.z); atomicAdd(&S[11*260 + j], v2.w);
        atomicAdd(&S[12*260 + j], v3.x); atomicAdd(&S[13*260 + j], v3.y);
        atomicAdd(&S[14*260 + j], v3.z); atomicAdd(&S[15*260 + j], v3.w);
    }
    __syncthreads();

    const int d = tid;     // 256 threads = 256 d
    float tau[16];
    #pragma unroll
    for (int a = 0; a < 16; a++) tau[a] = 0.f;
    for (int j4 = 0; j4 < 64; j4++) {
        int j = j4 * 4;
        float e0 = __ldg(&emb[(j+0)*D + d]);
        float e1 = __ldg(&emb[(j+1)*D + d]);
        float e2 = __ldg(&emb[(j+2)*D + d]);
        float e3 = __ldg(&emb[(j+3)*D + d]);
        #pragma unroll
        for (int a = 0; a < 16; a++) {
            float4 s4 = *(const float4*)&S[a*260 + j];   // warp-uniform LDS.128
            tau[a] = fmaf(s4.x, e0, tau[a]);
            tau[a] = fmaf(s4.y, e1, tau[a]);
            tau[a] = fmaf(s4.z, e2, tau[a]);
            tau[a] = fmaf(s4.w, e3, tau[a]);
        }
    }
    float Ad = 0.f;
    #pragma unroll
    for (int a = 0; a < 16; a++)
        Ad = fmaf(__ldg(&W2[a0 + a]), tanhf(tau[a]), Ad);
    g_Apart[(chunk*BATCH + b)*D + d] = Ad;
}

// ---------------- K6: A combine + P = E@A + scores -------------------------
__global__ void k6_scoresP(const float* __restrict__ emb,
                           const float* __restrict__ lin_w,
                           const float* __restrict__ lin_b,
                           float* __restrict__ out) {
    __shared__ float As[D];
    const int b = blockIdx.x, tid = threadIdx.x;   // 256 threads
    float A = g_Apart[(0*BATCH + b)*D + tid]
            + g_Apart[(1*BATCH + b)*D + tid]
            + g_Apart[(2*BATCH + b)*D + tid]
            + g_Apart[(3*BATCH + b)*D + tid];
    As[tid] = A;
    __syncthreads();

    {
        const int j = tid;
        float acc = 0.f;
        for (int d4 = 0; d4 < 64; d4++) {
            float4 e = __ldg((const float4*)&emb[j*D + d4*4]);
            float4 a = *(const float4*)&As[d4*4];
            acc = fmaf(e.x, a.x, acc); acc = fmaf(e.y, a.y, acc);
            acc = fmaf(e.z, a.z, acc); acc = fmaf(e.w, a.w, acc);
        }
        g_P[b*D + j] = acc;
    }
    if (tid < SECTORS) {
        float sa = 0.f;
        const float* lw = lin_w + tid*D;
        for (int dd = 0; dd < D; dd++) sa = fmaf(As[dd], __ldg(&lw[dd]), sa);
        out[ATT_SIZE + b*SECTORS + tid] = sa + lin_b[tid];
    }
}

// ---------------- K7: att = softmax over l of P[b, idx[b,l]] ---------------
__global__ __launch_bounds__(256) void k7_softmax(float* __restrict__ out) {
    __shared__ float Ps[D];
    __shared__ float red[256];
    const int b = blockIdx.x, tid = threadIdx.x;
    Ps[tid] = g_P[b*D + tid];
    __syncthreads();

    const int* idxb = g_idx + b*L;
    float z[8];
    float m = -3.0e38f;
    #pragma unroll
    for (int k = 0; k < 8; k++) {
        int l = tid + k*256;
        if (l < L) { z[k] = Ps[idxb[l]]; m = fmaxf(m, z[k]); }
        else z[k] = -3.0e38f;
    }
    red[tid] = m; __syncthreads();
    for (int st = 128; st > 0; st >>= 1) { if (tid < st) red[tid] = fmaxf(red[tid], red[tid+st]); __syncthreads(); }
    const float M = red[0]; __syncthreads();

    float s = 0.f;
    float ez[8];
    #pragma unroll
    for (int k = 0; k < 8; k++) {
        int l = tid + k*256;
        if (l < L) { ez[k] = expf(z[k] - M); s += ez[k]; }
        else ez[k] = 0.f;
    }
    red[tid] = s; __syncthreads();
    for (int st = 128; st > 0; st >>= 1) { if (tid < st) red[tid] += red[tid+st]; __syncthreads(); }
    const float inv = 1.f / red[0];
    #pragma unroll
    for (int k = 0; k < 8; k++) {
        int l = tid + k*256;
        if (l < L) out[b*L + l] = ez[k] * inv;
    }
}

// ---------------- launcher -------------------------------------------------
extern "C" void kernel_launch(void* const* d_in, const int* in_sizes, int n_in,
                              void* d_out, int out_size) {
    const float* x        = (const float*)d_in[0];
    const float* conv1_w  = (const float*)d_in[1];
    const float* conv1_b  = (const float*)d_in[2];
    const float* bn_gamma = (const float*)d_in[3];
    const float* bn_beta  = (const float*)d_in[4];
    const float* conv2_w  = (const float*)d_in[5];
    const float* conv2_b  = (const float*)d_in[6];
    const float* emb      = (const float*)d_in[7];
    const float* W1       = (const float*)d_in[8];
    const float* W2       = (const float*)d_in[9];
    const float* lin_w    = (const float*)d_in[10];
    const float* lin_b    = (const float*)d_in[11];
    float* out = (float*)d_out;

    k0_prep<<<512, 256>>>(conv1_w, W1);
    dim3 g1(NTILE, BATCH);
    k1_conv1<<<g1, 512>>>(x, conv1_b);
    k2_bn<<<F, 256>>>();
    dim3 g4(16, BATCH);
    k4_conv2<<<g4, 256>>>(bn_gamma, bn_beta, conv2_w, conv2_b);
    dim3 g5(4, BATCH);
    k5_att<<<g5, 256>>>(emb, W2);
    k6_scoresP<<<BATCH, 256>>>(emb, lin_w, lin_b, out);
    k7_softmax<<<BATCH, 256>>>(out);
}

// round 5
// speedup vs baseline: 5.1732x; 5.1732x over previous
#include <cuda_runtime.h>
#include <math.h>

// ---------------- problem constants ----------------
#define BATCH   64
#define CIN     32
#define T_IN    2048
#define F       64
#define WIN     5
#define TPOOL   2040            // after conv(valid)+maxpool5
#define L       2036            // after conv2
#define D       256
#define DA      64
#define SECTORS 11
#define ATT_SIZE (BATCH*L)

// conv1 tiling: 512 threads = 64 filters x 8 groups, 13 pooled / 17 conv / 21 x per group
#define GROUPS     8
#define POOL_PER_G 13
#define CONV_PER_G 17
#define XS_W       112
#define TILE_P     (GROUPS*POOL_PER_G)   // 104
#define NTILE      20                    // 20*104 = 2080 >= 2040
#define NBLK1      (BATCH*NTILE)         // 1280

// ---------------- device scratch (static: no allocations allowed) ----------
__device__ float  g_wT[CIN*WIN*F];        // conv1 weights as [c][k][f]
__device__ float  g_W1T[L*DA];            // W1 transposed: [l][a]
__device__ float  g_hp[BATCH*TPOOL*F];    // pooled conv1 output (fp32), layout [b][p][f]
__device__ float  g_psum[NBLK1*F];
__device__ float  g_psq [NBLK1*F];
__device__ float  g_muf[F];               // fp32-rounded exact mean
__device__ float  g_rf [F];               // fp32-rounded exact rsqrt(fl(var)+1e-5f)
__device__ int    g_idx[BATCH*L];         // quantization bucket per (b,l), in [0,255]
__device__ float  g_Apart[4*BATCH*D];     // partial A over a-chunks
__device__ float  g_P[BATCH*D];           // P[b][j] = emb[j,:] . A[b,:]

// ---------------- K0: weight reshapes -------------------------------------
__global__ void k0_prep(const float* __restrict__ conv1_w,
                        const float* __restrict__ W1) {
    int i = blockIdx.x * blockDim.x + threadIdx.x;
    int stride = gridDim.x * blockDim.x;
    for (int j = i; j < CIN*WIN*F; j += stride) {
        int f = j % F;
        int ck = j / F;
        int k = ck % WIN;
        int c = ck / WIN;
        g_wT[j] = conv1_w[(f*CIN + c)*WIN + k];
    }
    for (int j = i; j < L*DA; j += stride) {
        int a = j % DA;
        int l = j / DA;
        g_W1T[j] = W1[a*L + l];
    }
}

// ---------------- K1: conv1 (fp32 Kahan accum) + maxpool5 + BN partials ----
// grid (NTILE, BATCH), 512 threads = 64 filters x 8 t-groups.
// Per 2-channel group: fp32 10-tap fma chain (err ~5e-8), Kahan-merged into
// the accumulator (error ~1 ulp of h, term-count independent). No fp64.
__global__ __launch_bounds__(512) void k1_conv1(const float* __restrict__ x,
                                                const float* __restrict__ conv1_b) {
    __shared__ float xs[CIN][XS_W];
    __shared__ float s_part[2][GROUPS][F];
    const int b    = blockIdx.y;
    const int tile = blockIdx.x;
    const int p0   = tile * TILE_P;
    const int tid  = threadIdx.x;

    const float* xb = x + (size_t)b * CIN * T_IN;
    for (int i = tid; i < CIN*XS_W; i += 512) {
        int c = i / XS_W, t = i - c*XS_W;
        int gt = p0 + t;
        if (gt > T_IN-1) gt = T_IN-1;        // clamped values never feed valid outputs
        xs[c][t] = xb[c*T_IN + gt];
    }
    __syncthreads();

    const int f    = tid & 63;
    const int g    = tid >> 6;
    const int base = g * POOL_PER_G;

    float acc[CONV_PER_G], comp[CONV_PER_G];
    {
        float bias = __ldg(&conv1_b[f]);
        #pragma unroll
        for (int t = 0; t < CONV_PER_G; t++) { acc[t] = bias; comp[t] = 0.f; }
    }

    #pragma unroll 4
    for (int cp = 0; cp < CIN/2; cp++) {
        float cacc[CONV_PER_G];
        // channel 2*cp: start chains
        {
            const int c = 2*cp;
            float wv[WIN];
            #pragma unroll
            for (int k = 0; k < WIN; k++) wv[k] = __ldg(&g_wT[(c*WIN + k)*F + f]);
            float xv[CONV_PER_G + WIN - 1];
            #pragma unroll
            for (int t = 0; t < CONV_PER_G + WIN - 1; t++) xv[t] = xs[c][base + t];
            #pragma unroll
            for (int t = 0; t < CONV_PER_G; t++) {
                float a = __fmul_rn(xv[t], wv[0]);
                a = fmaf(xv[t+1], wv[1], a);
                a = fmaf(xv[t+2], wv[2], a);
                a = fmaf(xv[t+3], wv[3], a);
                a = fmaf(xv[t+4], wv[4], a);
                cacc[t] = a;
            }
        }
        // channel 2*cp+1: extend chains
        {
            const int c = 2*cp + 1;
            float wv[WIN];
            #pragma unroll
            for (int k = 0; k < WIN; k++) wv[k] = __ldg(&g_wT[(c*WIN + k)*F + f]);
            float xv[CONV_PER_G + WIN - 1];
            #pragma unroll
            for (int t = 0; t < CONV_PER_G + WIN - 1; t++) xv[t] = xs[c][base + t];
            #pragma unroll
            for (int t = 0; t < CONV_PER_G; t++) {
                float a = cacc[t];
                a = fmaf(xv[t  ], wv[0], a);
                a = fmaf(xv[t+1], wv[1], a);
                a = fmaf(xv[t+2], wv[2], a);
                a = fmaf(xv[t+3], wv[3], a);
                a = fmaf(xv[t+4], wv[4], a);
                cacc[t] = a;
            }
        }
        // Kahan merge (intrinsics: immune to reassociation)
        #pragma unroll
        for (int t = 0; t < CONV_PER_G; t++) {
            float y  = __fsub_rn(cacc[t], comp[t]);
            float s2 = __fadd_rn(acc[t], y);
            comp[t]  = __fsub_rn(__fsub_rn(s2, acc[t]), y);
            acc[t]   = s2;
        }
    }

    float hc[CONV_PER_G];
    #pragma unroll
    for (int t = 0; t < CONV_PER_G; t++) hc[t] = __fsub_rn(acc[t], comp[t]);

    // maxpool(5, stride 1) thread-local; store [b][p][f] (coalesced)
    float s = 0.f, sq = 0.f;
    float* hpb = g_hp + (size_t)b * TPOOL * F;
    #pragma unroll
    for (int t = 0; t < POOL_PER_G; t++) {
        float m = hc[t];
        m = fmaxf(m, hc[t+1]); m = fmaxf(m, hc[t+2]);
        m = fmaxf(m, hc[t+3]); m = fmaxf(m, hc[t+4]);
        int p = p0 + base + t;
        if (p < TPOOL) {
            hpb[p*F + f] = m;
            s  += m;
            sq = fmaf(m, m, sq);
        }
    }
    s_part[0][g][f] = s;
    s_part[1][g][f] = sq;
    __syncthreads();
    if (g == 0) {   // deterministic fixed-order combine
        float ts = 0.f, tq = 0.f;
        #pragma unroll
        for (int gg = 0; gg < GROUPS; gg++) { ts += s_part[0][gg][f]; tq += s_part[1][gg][f]; }
        int blk = b*NTILE + tile;
        g_psum[blk*F + f] = ts;
        g_psq [blk*F + f] = tq;
    }
}

// ---------------- K2: exact-enough BN reduce -> fp32 mu and rsqrt ----------
__global__ void k2_bn(void) {
    __shared__ double red[256];
    const int f = blockIdx.x, tid = threadIdx.x;
    double s = 0.0;
    for (int i = tid; i < NBLK1; i += 256) s += (double)g_psum[i*F + f];
    red[tid] = s; __syncthreads();
    for (int st = 128; st > 0; st >>= 1) { if (tid < st) red[tid] += red[tid+st]; __syncthreads(); }
    double tot = red[0]; __syncthreads();
    double q = 0.0;
    for (int i = tid; i < NBLK1; i += 256) q += (double)g_psq[i*F + f];
    red[tid] = q; __syncthreads();
    for (int st = 128; st > 0; st >>= 1) { if (tid < st) red[tid] += red[tid+st]; __syncthreads(); }
    if (tid == 0) {
        const double cnt = (double)BATCH * TPOOL;
        double mu  = tot / cnt;
        double var = red[0] / cnt - mu*mu;
        float muf  = (float)mu;
        float varf = (float)var;                        // ref's var is an fp32 value
        float sf   = __fadd_rn(varf, 1e-5f);            // ref: var + BN_EPS in fp32
        double r   = 1.0 / sqrt((double)sf);            // correctly-rounded rsqrt
        g_muf[f] = muf;
        g_rf [f] = (float)r;
    }
}

// ---------------- K4: fp32 BN steps + conv2 (fp32 Kahan) + sigmoid -> idx --
// grid (16, BATCH), 256 threads; tile of 128 l.
// BN applied at tile load with the reference's exact fp32 step order.
// conv2: per-product Kahan accumulation (delta ~1 ulp); half-combine in double.
__global__ __launch_bounds__(256) void k4_conv2(const float* __restrict__ bn_gamma,
                                                const float* __restrict__ bn_beta,
                                                const float* __restrict__ conv2_w,
                                                const float* __restrict__ conv2_b) {
    __shared__ float  hps[132*65];       // padded stride 65 -> conflict-free
    __shared__ float  w2s[F*WIN];
    __shared__ float2 part2[2][128];
    const int b  = blockIdx.y;
    const int l0 = blockIdx.x * 128;
    const int tid = threadIdx.x;

    const float* hpb = g_hp + (size_t)b * TPOOL * F;
    for (int i = tid; i < 132*F; i += 256) {
        int p = i >> 6, f = i & 63;
        int gp = l0 + p;
        if (gp > TPOOL-1) gp = TPOOL-1;               // feeds only discarded l
        float h  = hpb[gp*F + f];
        float t1 = __fsub_rn(h,  g_muf[f]);
        float t2 = __fmul_rn(t1, g_rf[f]);
        float t3 = __fmul_rn(t2, bn_gamma[f]);
        float t4 = __fadd_rn(t3, bn_beta[f]);
        hps[p*65 + f] = t4;
    }
    for (int i = tid; i < F*WIN; i += 256) w2s[i] = conv2_w[i];
    __syncthreads();

    const int half = tid >> 7, lloc = tid & 127;
    const int f0 = half * 32;
    float vs = 0.f, vc = 0.f;
    for (int f = f0; f < f0 + 32; f++) {
        #pragma unroll
        for (int k = 0; k < WIN; k++) {
            float p = __fmul_rn(hps[(lloc+k)*65 + f], w2s[f*WIN + k]);
            float y = __fsub_rn(p, vc);
            float t = __fadd_rn(vs, y);
            vc = __fsub_rn(__fsub_rn(t, vs), y);
            vs = t;
        }
    }
    part2[half][lloc] = make_float2(vs, vc);
    __syncthreads();
    if (half == 0) {
        int l = l0 + lloc;
        if (l < L) {
            float2 q0 = part2[0][lloc], q1 = part2[1][lloc];
            double vd = ((double)q0.x - (double)q0.y)
                      + ((double)q1.x - (double)q1.y)
                      + (double)conv2_b[0];
            float vf = (float)vd;                       // ref conv2 output is fp32
            vf = fmaxf(vf, 0.f);                        // relu (fp32, exact)
            double cd = 1.0 / (1.0 + exp(-(double)vf)); // true sigmoid of fp32 v
            float cf = (float)cd;                       // round c to fp32 like ref
            float pf = __fmul_rn(cf, 256.0f);           // exact (x2^8)
            int id = (int)ceilf(pf) - 1;
            id = min(max(id, 0), 255);
            g_idx[b*L + l] = id;
        }
    }
}

// ---------------- K5: bucket scatter + tau = S@E + tanh + partial A --------
// grid (4 a-chunks, BATCH), 256 threads. S in shared (16 x 260 padded).
__global__ __launch_bounds__(256) void k5_att(const float* __restrict__ emb,
                                              const float* __restrict__ W2) {
    __shared__ float S[16*260];   // stride 260: float4-aligned, banks spread
    const int b = blockIdx.y, chunk = blockIdx.x;
    const int a0 = chunk * 16;
    const int tid = threadIdx.x;

    for (int i = tid; i < 16*260; i += 256) S[i] = 0.f;
    __syncthreads();

    const int* idxb = g_idx + b*L;
    for (int l = tid; l < L; l += 256) {
        int j = idxb[l];
        const float4* w4 = (const float4*)(g_W1T + l*DA + a0);
        float4 v0 = w4[0], v1 = w4[1], v2 = w4[2], v3 = w4[3];
        atomicAdd(&S[ 0*260 + j], v0.x); atomicAdd(&S[ 1*260 + j], v0.y);
        atomicAdd(&S[ 2*260 + j], v0.z); atomicAdd(&S[ 3*260 + j], v0.w);
        atomicAdd(&S[ 4*260 + j], v1.x); atomicAdd(&S[ 5*260 + j], v1.y);
        atomicAdd(&S[ 6*260 + j], v1.z); atomicAdd(&S[ 7*260 + j], v1.w);
        atomicAdd(&S[ 8*260 + j], v2.x); atomicAdd(&S[ 9*260 + j], v2.y);
        atomicAdd(&S[10*260 + j], v2.z); atomicAdd(&S[11*260 + j], v2.w);
        atomicAdd(&S[12*260 + j], v3.x); atomicAdd(&S[13*260 + j], v3.y);
        atomicAdd(&S[14*260 + j], v3.z); atomicAdd(&S[15*260 + j], v3.w);
    }
    __syncthreads();

    const int d = tid;     // 256 threads = 256 d
    float tau[16];
    #pragma unroll
    for (int a = 0; a < 16; a++) tau[a] = 0.f;
    for (int j4 = 0; j4 < 64; j4++) {
        int j = j4 * 4;
        float e0 = __ldg(&emb[(j+0)*D + d]);
        float e1 = __ldg(&emb[(j+1)*D + d]);
        float e2 = __ldg(&emb[(j+2)*D + d]);
        float e3 = __ldg(&emb[(j+3)*D + d]);
        #pragma unroll
        for (int a = 0; a < 16; a++) {
            float4 s4 = *(const float4*)&S[a*260 + j];   // warp-uniform LDS.128
            tau[a] = fmaf(s4.x, e0, tau[a]);
            tau[a] = fmaf(s4.y, e1, tau[a]);
            tau[a] = fmaf(s4.z, e2, tau[a]);
            tau[a] = fmaf(s4.w, e3, tau[a]);
        }
    }
    float Ad = 0.f;
    #pragma unroll
    for (int a = 0; a < 16; a++)
        Ad = fmaf(__ldg(&W2[a0 + a]), tanhf(tau[a]), Ad);
    g_Apart[(chunk*BATCH + b)*D + d] = Ad;
}

// ---------------- K6: A combine + P = E@A + scores -------------------------
__global__ void k6_scoresP(const float* __restrict__ emb,
                           const float* __restrict__ lin_w,
                           const float* __restrict__ lin_b,
                           float* __restrict__ out) {
    __shared__ float As[D];
    const int b = blockIdx.x, tid = threadIdx.x;   // 256 threads
    float A = g_Apart[(0*BATCH + b)*D + tid]
            + g_Apart[(1*BATCH + b)*D + tid]
            + g_Apart[(2*BATCH + b)*D + tid]
            + g_Apart[(3*BATCH + b)*D + tid];
    As[tid] = A;
    __syncthreads();

    {
        const int j = tid;
        float acc = 0.f;
        for (int d4 = 0; d4 < 64; d4++) {
            float4 e = __ldg((const float4*)&emb[j*D + d4*4]);
            float4 a = *(const float4*)&As[d4*4];
            acc = fmaf(e.x, a.x, acc); acc = fmaf(e.y, a.y, acc);
            acc = fmaf(e.z, a.z, acc); acc = fmaf(e.w, a.w, acc);
        }
        g_P[b*D + j] = acc;
    }
    if (tid < SECTORS) {
        float sa = 0.f;
        const float* lw = lin_w + tid*D;
        for (int dd = 0; dd < D; dd++) sa = fmaf(As[dd], __ldg(&lw[dd]), sa);
        out[ATT_SIZE + b*SECTORS + tid] = sa + lin_b[tid];
    }
}

// ---------------- K7: att = softmax over l of P[b, idx[b,l]] ---------------
__global__ __launch_bounds__(256) void k7_softmax(float* __restrict__ out) {
    __shared__ float Ps[D];
    __shared__ float red[256];
    const int b = blockIdx.x, tid = threadIdx.x;
    Ps[tid] = g_P[b*D + tid];
    __syncthreads();

    const int* idxb = g_idx + b*L;
    float z[8];
    float m = -3.0e38f;
    #pragma unroll
    for (int k = 0; k < 8; k++) {
        int l = tid + k*256;
        if (l < L) { z[k] = Ps[idxb[l]]; m = fmaxf(m, z[k]); }
        else z[k] = -3.0e38f;
    }
    red[tid] = m; __syncthreads();
    for (int st = 128; st > 0; st >>= 1) { if (tid < st) red[tid] = fmaxf(red[tid], red[tid+st]); __syncthreads(); }
    const float M = red[0]; __syncthreads();

    float s = 0.f;
    float ez[8];
    #pragma unroll
    for (int k = 0; k < 8; k++) {
        int l = tid + k*256;
        if (l < L) { ez[k] = expf(z[k] - M); s += ez[k]; }
        else ez[k] = 0.f;
    }
    red[tid] = s; __syncthreads();
    for (int st = 128; st > 0; st >>= 1) { if (tid < st) red[tid] += red[tid+st]; __syncthreads(); }
    const float inv = 1.f / red[0];
    #pragma unroll
    for (int k = 0; k < 8; k++) {
        int l = tid + k*256;
        if (l < L) out[b*L + l] = ez[k] * inv;
    }
}

// ---------------- launcher -------------------------------------------------
extern "C" void kernel_launch(void* const* d_in, const int* in_sizes, int n_in,
                              void* d_out, int out_size) {
    const float* x        = (const float*)d_in[0];
    const float* conv1_w  = (const float*)d_in[1];
    const float* conv1_b  = (const float*)d_in[2];
    const float* bn_gamma = (const float*)d_in[3];
    const float* bn_beta  = (const float*)d_in[4];
    const float* conv2_w  = (const float*)d_in[5];
    const float* conv2_b  = (const float*)d_in[6];
    const float* emb      = (const float*)d_in[7];
    const float* W1       = (const float*)d_in[8];
    const float* W2       = (const float*)d_in[9];
    const float* lin_w    = (const float*)d_in[10];
    const float* lin_b    = (const float*)d_in[11];
    float* out = (float*)d_out;

    k0_prep<<<512, 256>>>(conv1_w, W1);
    dim3 g1(NTILE, BATCH);
    k1_conv1<<<g1, 512>>>(x, conv1_b);
    k2_bn<<<F, 256>>>();
    dim3 g4(16, BATCH);
    k4_conv2<<<g4, 256>>>(bn_gamma, bn_beta, conv2_w, conv2_b);
    dim3 g5(4, BATCH);
    k5_att<<<g5, 256>>>(emb, W2);
    k6_scoresP<<<BATCH, 256>>>(emb, lin_w, lin_b, out);
    k7_softmax<<<BATCH, 256>>>(out);
}

// round 6
// speedup vs baseline: 5.2890x; 1.0224x over previous
#include <cuda_runtime.h>
#include <math.h>

// ---------------- problem constants ----------------
#define BATCH   64
#define CIN     32
#define T_IN    2048
#define F       64
#define WIN     5
#define TPOOL   2040            // after conv(valid)+maxpool5
#define L       2036            // after conv2
#define D       256
#define DA      64
#define SECTORS 11
#define ATT_SIZE (BATCH*L)

// conv1 tiling: 512 threads = 64 filters x 8 groups, 14 pooled / 18 conv / 22 x per group
#define GROUPS     8
#define POOL_PER_G 14
#define CONV_PER_G 18
#define PAIRS      9            // conv outputs as f32x2 pairs
#define XS_W       120
#define TILE_P     (GROUPS*POOL_PER_G)   // 112
#define NTILE      19                    // 19*112 = 2128 >= 2040
#define NBLK1     (BATCH*NTILE)          // 1216

typedef unsigned long long u64;

// ---- f32x2 packed helpers (each half rounds identically to scalar) --------
__device__ __forceinline__ u64 pk2(float lo, float hi) {
    u64 r; asm("mov.b64 %0, {%1,%2};" : "=l"(r) : "f"(lo), "f"(hi)); return r;
}
__device__ __forceinline__ void upk2(float& lo, float& hi, u64 v) {
    asm("mov.b64 {%0,%1}, %2;" : "=f"(lo), "=f"(hi) : "l"(v));
}
__device__ __forceinline__ u64 fma2(u64 a, u64 b, u64 c) {
    u64 d; asm("fma.rn.f32x2 %0, %1, %2, %3;" : "=l"(d) : "l"(a), "l"(b), "l"(c)); return d;
}
__device__ __forceinline__ u64 mul2(u64 a, u64 b) {
    u64 d; asm("mul.rn.f32x2 %0, %1, %2;" : "=l"(d) : "l"(a), "l"(b)); return d;
}
__device__ __forceinline__ u64 add2(u64 a, u64 b) {
    u64 d; asm("add.rn.f32x2 %0, %1, %2;" : "=l"(d) : "l"(a), "l"(b)); return d;
}

// ---------------- device scratch (static: no allocations allowed) ----------
__device__ float  g_wT[CIN*WIN*F];        // conv1 weights as [c][k][f]
__device__ float  g_W1T[L*DA];            // W1 transposed: [l][a]
__device__ float  g_hp[BATCH*TPOOL*F];    // pooled conv1 output (fp32), layout [b][p][f]
__device__ float  g_psum[NBLK1*F];
__device__ float  g_psq [NBLK1*F];
__device__ float  g_muf[F];               // fp32-rounded exact mean
__device__ float  g_rf [F];               // fp32-rounded exact rsqrt(fl(var)+1e-5f)
__device__ int    g_idx[BATCH*L];         // quantization bucket per (b,l), in [0,255]
__device__ float  g_Apart[4*BATCH*D];     // partial A over a-chunks
__device__ float  g_P[BATCH*D];           // P[b][j] = emb[j,:] . A[b,:]

// ---------------- K0: weight reshapes -------------------------------------
__global__ void k0_prep(const float* __restrict__ conv1_w,
                        const float* __restrict__ W1) {
    int i = blockIdx.x * blockDim.x + threadIdx.x;
    int stride = gridDim.x * blockDim.x;
    for (int j = i; j < CIN*WIN*F; j += stride) {
        int f = j % F;
        int ck = j / F;
        int k = ck % WIN;
        int c = ck / WIN;
        g_wT[j] = conv1_w[(f*CIN + c)*WIN + k];
    }
    for (int j = i; j < L*DA; j += stride) {
        int a = j % DA;
        int l = j / DA;
        g_W1T[j] = W1[a*L + l];
    }
}

// ---------------- K1: conv1 (f32x2 FMA chains + packed Kahan) --------------
// grid (NTILE, BATCH), 512 threads = 64 filters x 8 t-groups.
// Conv pair p covers outputs t=2p,2p+1. Tap k uses x-pair (xv[2p+k], xv[2p+k+1]):
// even k = aligned LDS.64, odd k = one mov.b64 pack. Each f32x2 half rounds
// exactly like the scalar FFMA -> h is bit-identical to the scalar Kahan version.
__global__ __launch_bounds__(512) void k1_conv1(const float* __restrict__ x,
                                                const float* __restrict__ conv1_b) {
    __shared__ float xs[CIN][XS_W];
    __shared__ float s_part[2][GROUPS][F];
    const int b    = blockIdx.y;
    const int tile = blockIdx.x;
    const int p0   = tile * TILE_P;
    const int tid  = threadIdx.x;

    const float* xb = x + (size_t)b * CIN * T_IN;
    for (int i = tid; i < CIN*XS_W; i += 512) {
        int c = i / XS_W, t = i - c*XS_W;
        int gt = p0 + t;
        if (gt > T_IN-1) gt = T_IN-1;        // clamped values never feed valid outputs
        xs[c][t] = xb[c*T_IN + gt];
    }
    __syncthreads();

    const int f    = tid & 63;
    const int g    = tid >> 6;
    const int base = g * POOL_PER_G;         // even -> 8B-aligned pair loads

    u64 acc2[PAIRS], nc2[PAIRS];             // Kahan with sign-flipped compensation
    const u64 NEG1 = pk2(-1.f, -1.f);
    const u64 Z2   = pk2(0.f, 0.f);
    {
        float bias = __ldg(&conv1_b[f]);
        u64 b2 = pk2(bias, bias);
        #pragma unroll
        for (int p = 0; p < PAIRS; p++) { acc2[p] = b2; nc2[p] = Z2; }
    }

    #pragma unroll 1
    for (int cp = 0; cp < CIN/2; cp++) {
        u64 cacc[PAIRS];
        // ---- even channel: start chains (mul first, as scalar version) ----
        {
            const int c = 2*cp;
            const float* xrow = &xs[c][base];
            u64 E[11]; float el[11], eh[11];
            #pragma unroll
            for (int i = 0; i < 11; i++) { E[i] = *(const u64*)(xrow + 2*i); upk2(el[i], eh[i], E[i]); }
            u64 O[10];
            #pragma unroll
            for (int i = 0; i < 10; i++) O[i] = pk2(eh[i], el[i+1]);
            u64 W[WIN];
            #pragma unroll
            for (int k = 0; k < WIN; k++) { float w = __ldg(&g_wT[(c*WIN + k)*F + f]); W[k] = pk2(w, w); }
            #pragma unroll
            for (int p = 0; p < PAIRS; p++) {
                u64 a = mul2(E[p], W[0]);
                a = fma2(O[p],   W[1], a);
                a = fma2(E[p+1], W[2], a);
                a = fma2(O[p+1], W[3], a);
                a = fma2(E[p+2], W[4], a);
                cacc[p] = a;
            }
        }
        // ---- odd channel: extend chains ----
        {
            const int c = 2*cp + 1;
            const float* xrow = &xs[c][base];
            u64 E[11]; float el[11], eh[11];
            #pragma unroll
            for (int i = 0; i < 11; i++) { E[i] = *(const u64*)(xrow + 2*i); upk2(el[i], eh[i], E[i]); }
            u64 O[10];
            #pragma unroll
            for (int i = 0; i < 10; i++) O[i] = pk2(eh[i], el[i+1]);
            u64 W[WIN];
            #pragma unroll
            for (int k = 0; k < WIN; k++) { float w = __ldg(&g_wT[(c*WIN + k)*F + f]); W[k] = pk2(w, w); }
            #pragma unroll
            for (int p = 0; p < PAIRS; p++) {
                u64 a = cacc[p];
                a = fma2(E[p],   W[0], a);
                a = fma2(O[p],   W[1], a);
                a = fma2(E[p+1], W[2], a);
                a = fma2(O[p+1], W[3], a);
                a = fma2(E[p+2], W[4], a);
                cacc[p] = a;
            }
        }
        // ---- packed Kahan merge (bit-identical to scalar: RN symmetric) ---
        #pragma unroll
        for (int p = 0; p < PAIRS; p++) {
            u64 y   = add2(cacc[p], nc2[p]);       //  v - c
            u64 s2  = add2(acc2[p], y);            //  s + y
            u64 ns2 = fma2(s2, NEG1, Z2);          // -s2 (exact)
            u64 d   = add2(acc2[p], ns2);          //  s - s2 (== -(s2-s))
            nc2[p]  = add2(d, y);                  // -((s2-s) - y)
            acc2[p] = s2;
        }
    }

    float hc[CONV_PER_G];
    #pragma unroll
    for (int p = 0; p < PAIRS; p++) {
        u64 h2 = add2(acc2[p], nc2[p]);            // acc - comp
        upk2(hc[2*p], hc[2*p+1], h2);
    }

    // maxpool(5, stride 1) thread-local; store [b][p][f] (coalesced)
    float s = 0.f, sq = 0.f;
    float* hpb = g_hp + (size_t)b * TPOOL * F;
    #pragma unroll
    for (int t = 0; t < POOL_PER_G; t++) {
        float m = hc[t];
        m = fmaxf(m, hc[t+1]); m = fmaxf(m, hc[t+2]);
        m = fmaxf(m, hc[t+3]); m = fmaxf(m, hc[t+4]);
        int p = p0 + base + t;
        if (p < TPOOL) {
            hpb[p*F + f] = m;
            s  += m;
            sq = fmaf(m, m, sq);
        }
    }
    s_part[0][g][f] = s;
    s_part[1][g][f] = sq;
    __syncthreads();
    if (g == 0) {   // deterministic fixed-order combine
        float ts = 0.f, tq = 0.f;
        #pragma unroll
        for (int gg = 0; gg < GROUPS; gg++) { ts += s_part[0][gg][f]; tq += s_part[1][gg][f]; }
        int blk = b*NTILE + tile;
        g_psum[blk*F + f] = ts;
        g_psq [blk*F + f] = tq;
    }
}

// ---------------- K2: exact-enough BN reduce -> fp32 mu and rsqrt ----------
__global__ void k2_bn(void) {
    __shared__ double red[256];
    const int f = blockIdx.x, tid = threadIdx.x;
    double s = 0.0;
    for (int i = tid; i < NBLK1; i += 256) s += (double)g_psum[i*F + f];
    red[tid] = s; __syncthreads();
    for (int st = 128; st > 0; st >>= 1) { if (tid < st) red[tid] += red[tid+st]; __syncthreads(); }
    double tot = red[0]; __syncthreads();
    double q = 0.0;
    for (int i = tid; i < NBLK1; i += 256) q += (double)g_psq[i*F + f];
    red[tid] = q; __syncthreads();
    for (int st = 128; st > 0; st >>= 1) { if (tid < st) red[tid] += red[tid+st]; __syncthreads(); }
    if (tid == 0) {
        const double cnt = (double)BATCH * TPOOL;
        double mu  = tot / cnt;
        double var = red[0] / cnt - mu*mu;
        float muf  = (float)mu;
        float varf = (float)var;                        // ref's var is an fp32 value
        float sf   = __fadd_rn(varf, 1e-5f);            // ref: var + BN_EPS in fp32
        double r   = 1.0 / sqrt((double)sf);            // correctly-rounded rsqrt
        g_muf[f] = muf;
        g_rf [f] = (float)r;
    }
}

// ---------------- K4: fp32 BN steps + conv2 (fp32 Kahan) + sigmoid -> idx --
__global__ __launch_bounds__(256) void k4_conv2(const float* __restrict__ bn_gamma,
                                                const float* __restrict__ bn_beta,
                                                const float* __restrict__ conv2_w,
                                                const float* __restrict__ conv2_b) {
    __shared__ float  hps[132*65];       // padded stride 65 -> conflict-free
    __shared__ float  w2s[F*WIN];
    __shared__ float2 part2[2][128];
    const int b  = blockIdx.y;
    const int l0 = blockIdx.x * 128;
    const int tid = threadIdx.x;

    const float* hpb = g_hp + (size_t)b * TPOOL * F;
    for (int i = tid; i < 132*F; i += 256) {
        int p = i >> 6, f = i & 63;
        int gp = l0 + p;
        if (gp > TPOOL-1) gp = TPOOL-1;               // feeds only discarded l
        float h  = hpb[gp*F + f];
        float t1 = __fsub_rn(h,  g_muf[f]);
        float t2 = __fmul_rn(t1, g_rf[f]);
        float t3 = __fmul_rn(t2, bn_gamma[f]);
        float t4 = __fadd_rn(t3, bn_beta[f]);
        hps[p*65 + f] = t4;
    }
    for (int i = tid; i < F*WIN; i += 256) w2s[i] = conv2_w[i];
    __syncthreads();

    const int half = tid >> 7, lloc = tid & 127;
    const int f0 = half * 32;
    float vs = 0.f, vc = 0.f;
    for (int f = f0; f < f0 + 32; f++) {
        #pragma unroll
        for (int k = 0; k < WIN; k++) {
            float p = __fmul_rn(hps[(lloc+k)*65 + f], w2s[f*WIN + k]);
            float y = __fsub_rn(p, vc);
            float t = __fadd_rn(vs, y);
            vc = __fsub_rn(__fsub_rn(t, vs), y);
            vs = t;
        }
    }
    part2[half][lloc] = make_float2(vs, vc);
    __syncthreads();
    if (half == 0) {
        int l = l0 + lloc;
        if (l < L) {
            float2 q0 = part2[0][lloc], q1 = part2[1][lloc];
            double vd = ((double)q0.x - (double)q0.y)
                      + ((double)q1.x - (double)q1.y)
                      + (double)conv2_b[0];
            float vf = (float)vd;                       // ref conv2 output is fp32
            vf = fmaxf(vf, 0.f);                        // relu (fp32, exact)
            double cd = 1.0 / (1.0 + exp(-(double)vf)); // true sigmoid of fp32 v
            float cf = (float)cd;                       // round c to fp32 like ref
            float pf = __fmul_rn(cf, 256.0f);           // exact (x2^8)
            int id = (int)ceilf(pf) - 1;
            id = min(max(id, 0), 255);
            g_idx[b*L + l] = id;
        }
    }
}

// ---------------- K5: bucket scatter + tau = S@E + tanh + partial A --------
__global__ __launch_bounds__(256) void k5_att(const float* __restrict__ emb,
                                              const float* __restrict__ W2) {
    __shared__ float S[16*260];   // stride 260: float4-aligned, banks spread
    const int b = blockIdx.y, chunk = blockIdx.x;
    const int a0 = chunk * 16;
    const int tid = threadIdx.x;

    for (int i = tid; i < 16*260; i += 256) S[i] = 0.f;
    __syncthreads();

    const int* idxb = g_idx + b*L;
    for (int l = tid; l < L; l += 256) {
        int j = idxb[l];
        const float4* w4 = (const float4*)(g_W1T + l*DA + a0);
        float4 v0 = w4[0], v1 = w4[1], v2 = w4[2], v3 = w4[3];
        atomicAdd(&S[ 0*260 + j], v0.x); atomicAdd(&S[ 1*260 + j], v0.y);
        atomicAdd(&S[ 2*260 + j], v0.z); atomicAdd(&S[ 3*260 + j], v0.w);
        atomicAdd(&S[ 4*260 + j], v1.x); atomicAdd(&S[ 5*260 + j], v1.y);
        atomicAdd(&S[ 6*260 + j], v1.z); atomicAdd(&S[ 7*260 + j], v1.w);
        atomicAdd(&S[ 8*260 + j], v2.x); atomicAdd(&S[ 9*260 + j], v2.y);
        atomicAdd(&S[10*260 + j], v2.z); atomicAdd(&S[11*260 + j], v2.w);
        atomicAdd(&S[12*260 + j], v3.x); atomicAdd(&S[13*260 + j], v3.y);
        atomicAdd(&S[14*260 + j], v3.z); atomicAdd(&S[15*260 + j], v3.w);
    }
    __syncthreads();

    const int d = tid;     // 256 threads = 256 d
    float tau[16];
    #pragma unroll
    for (int a = 0; a < 16; a++) tau[a] = 0.f;
    for (int j4 = 0; j4 < 64; j4++) {
        int j = j4 * 4;
        float e0 = __ldg(&emb[(j+0)*D + d]);
        float e1 = __ldg(&emb[(j+1)*D + d]);
        float e2 = __ldg(&emb[(j+2)*D + d]);
        float e3 = __ldg(&emb[(j+3)*D + d]);
        #pragma unroll
        for (int a = 0; a < 16; a++) {
            float4 s4 = *(const float4*)&S[a*260 + j];   // warp-uniform LDS.128
            tau[a] = fmaf(s4.x, e0, tau[a]);
            tau[a] = fmaf(s4.y, e1, tau[a]);
            tau[a] = fmaf(s4.z, e2, tau[a]);
            tau[a] = fmaf(s4.w, e3, tau[a]);
        }
    }
    float Ad = 0.f;
    #pragma unroll
    for (int a = 0; a < 16; a++)
        Ad = fmaf(__ldg(&W2[a0 + a]), tanhf(tau[a]), Ad);
    g_Apart[(chunk*BATCH + b)*D + d] = Ad;
}

// ---------------- K6: A combine + P = E@A + scores -------------------------
__global__ void k6_scoresP(const float* __restrict__ emb,
                           const float* __restrict__ lin_w,
                           const float* __restrict__ lin_b,
                           float* __restrict__ out) {
    __shared__ float As[D];
    const int b = blockIdx.x, tid = threadIdx.x;   // 256 threads
    float A = g_Apart[(0*BATCH + b)*D + tid]
            + g_Apart[(1*BATCH + b)*D + tid]
            + g_Apart[(2*BATCH + b)*D + tid]
            + g_Apart[(3*BATCH + b)*D + tid];
    As[tid] = A;
    __syncthreads();

    {
        const int j = tid;
        float acc = 0.f;
        for (int d4 = 0; d4 < 64; d4++) {
            float4 e = __ldg((const float4*)&emb[j*D + d4*4]);
            float4 a = *(const float4*)&As[d4*4];
            acc = fmaf(e.x, a.x, acc); acc = fmaf(e.y, a.y, acc);
            acc = fmaf(e.z, a.z, acc); acc = fmaf(e.w, a.w, acc);
        }
        g_P[b*D + j] = acc;
    }
    if (tid < SECTORS) {
        float sa = 0.f;
        const float* lw = lin_w + tid*D;
        for (int dd = 0; dd < D; dd++) sa = fmaf(As[dd], __ldg(&lw[dd]), sa);
        out[ATT_SIZE + b*SECTORS + tid] = sa + lin_b[tid];
    }
}

// ---------------- K7: att = softmax over l of P[b, idx[b,l]] ---------------
__global__ __launch_bounds__(256) void k7_softmax(float* __restrict__ out) {
    __shared__ float Ps[D];
    __shared__ float red[256];
    const int b = blockIdx.x, tid = threadIdx.x;
    Ps[tid] = g_P[b*D + tid];
    __syncthreads();

    const int* idxb = g_idx + b*L;
    float z[8];
    float m = -3.0e38f;
    #pragma unroll
    for (int k = 0; k < 8; k++) {
        int l = tid + k*256;
        if (l < L) { z[k] = Ps[idxb[l]]; m = fmaxf(m, z[k]); }
        else z[k] = -3.0e38f;
    }
    red[tid] = m; __syncthreads();
    for (int st = 128; st > 0; st >>= 1) { if (tid < st) red[tid] = fmaxf(red[tid], red[tid+st]); __syncthreads(); }
    const float M = red[0]; __syncthreads();

    float s = 0.f;
    float ez[8];
    #pragma unroll
    for (int k = 0; k < 8; k++) {
        int l = tid + k*256;
        if (l < L) { ez[k] = expf(z[k] - M); s += ez[k]; }
        else ez[k] = 0.f;
    }
    red[tid] = s; __syncthreads();
    for (int st = 128; st > 0; st >>= 1) { if (tid < st) red[tid] += red[tid+st]; __syncthreads(); }
    const float inv = 1.f / red[0];
    #pragma unroll
    for (int k = 0; k < 8; k++) {
        int l = tid + k*256;
        if (l < L) out[b*L + l] = ez[k] * inv;
    }
}

// ---------------- launcher -------------------------------------------------
extern "C" void kernel_launch(void* const* d_in, const int* in_sizes, int n_in,
                              void* d_out, int out_size) {
    const float* x        = (const float*)d_in[0];
    const float* conv1_w  = (const float*)d_in[1];
    const float* conv1_b  = (const float*)d_in[2];
    const float* bn_gamma = (const float*)d_in[3];
    const float* bn_beta  = (const float*)d_in[4];
    const float* conv2_w  = (const float*)d_in[5];
    const float* conv2_b  = (const float*)d_in[6];
    const float* emb      = (const float*)d_in[7];
    const float* W1       = (const float*)d_in[8];
    const float* W2       = (const float*)d_in[9];
    const float* lin_w    = (const float*)d_in[10];
    const float* lin_b    = (const float*)d_in[11];
    float* out = (float*)d_out;

    k0_prep<<<512, 256>>>(conv1_w, W1);
    dim3 g1(NTILE, BATCH);
    k1_conv1<<<g1, 512>>>(x, conv1_b);
    k2_bn<<<F, 256>>>();
    dim3 g4(16, BATCH);
    k4_conv2<<<g4, 256>>>(bn_gamma, bn_beta, conv2_w, conv2_b);
    dim3 g5(4, BATCH);
    k5_att<<<g5, 256>>>(emb, W2);
    k6_scoresP<<<BATCH, 256>>>(emb, lin_w, lin_b, out);
    k7_softmax<<<BATCH, 256>>>(out);
}

// round 11
// speedup vs baseline: 9.5891x; 1.8130x over previous
#include <cuda_runtime.h>
#include <math.h>

// ---------------- problem constants ----------------
#define BATCH   64
#define CIN     32
#define T_IN    2048
#define F       64
#define WIN     5
#define TPOOL   2040            // after conv(valid)+maxpool5
#define L       2036            // after conv2
#define D       256
#define DA      64
#define SECTORS 11
#define ATT_SIZE (BATCH*L)

// conv1 tiling: 256 threads = 64 filters x 4 groups, 14 pooled / 18 conv / 22 x per group
#define GROUPS     4
#define POOL_PER_G 14
#define CONV_PER_G 18
#define PAIRS      9            // conv outputs as f32x2 pairs
#define XS_W       64
#define TILE_P     (GROUPS*POOL_PER_G)   // 56
#define NTILE      37                    // 37*56 = 2072 >= 2040
#define NBLK1      (BATCH*NTILE)         // 2368

// k5 chunking
#define CHUNKS  8
#define AC      8               // a-values per chunk

typedef unsigned long long u64;

// ---- f32x2 packed helpers (each half rounds identically to scalar) --------
__device__ __forceinline__ u64 pk2(float lo, float hi) {
    u64 r; asm("mov.b64 %0, {%1,%2};" : "=l"(r) : "f"(lo), "f"(hi)); return r;
}
__device__ __forceinline__ void upk2(float& lo, float& hi, u64 v) {
    asm("mov.b64 {%0,%1}, %2;" : "=f"(lo), "=f"(hi) : "l"(v));
}
__device__ __forceinline__ u64 fma2(u64 a, u64 b, u64 c) {
    u64 d; asm("fma.rn.f32x2 %0, %1, %2, %3;" : "=l"(d) : "l"(a), "l"(b), "l"(c)); return d;
}
__device__ __forceinline__ u64 add2(u64 a, u64 b) {
    u64 d; asm("add.rn.f32x2 %0, %1, %2;" : "=l"(d) : "l"(a), "l"(b)); return d;
}

// ---------------- device scratch (static: no allocations allowed) ----------
__device__ float  g_wT[CIN*WIN*F];        // conv1 weights as [c][k][f]
__device__ float  g_W1T[L*DA];            // W1 transposed: [l][a]
__device__ float  g_hp[BATCH*TPOOL*F];    // pooled conv1 output (fp32), layout [b][p][f]
__device__ float  g_psum[NBLK1*F];
__device__ float  g_psq [NBLK1*F];
__device__ float  g_muf[F];               // fp32-rounded exact mean
__device__ float  g_rf [F];               // fp32-rounded exact rsqrt(fl(var)+1e-5f)
__device__ int    g_idx[BATCH*L];         // quantization bucket per (b,l), in [0,255]
__device__ float  g_Apart[CHUNKS*BATCH*D];// partial A over a-chunks
__device__ float  g_P[BATCH*D];           // P[b][j] = emb[j,:] . A[b,:]

// ---------------- K0: weight reshapes -------------------------------------
__global__ void k0_prep(const float* __restrict__ conv1_w,
                        const float* __restrict__ W1) {
    int i = blockIdx.x * blockDim.x + threadIdx.x;
    int stride = gridDim.x * blockDim.x;
    for (int j = i; j < CIN*WIN*F; j += stride) {
        int f = j % F;
        int ck = j / F;
        int k = ck % WIN;
        int c = ck / WIN;
        g_wT[j] = conv1_w[(f*CIN + c)*WIN + k];
    }
    for (int j = i; j < L*DA; j += stride) {
        int a = j % DA;
        int l = j / DA;
        g_W1T[j] = W1[a*L + l];
    }
}

// ---------------- K1: conv1 (f32x2, 4-channel chains + packed Kahan) -------
// grid (NTILE, BATCH), 256 threads = 64 filters x 4 t-groups.
// 256-thread blocks: no 128-reg cap -> no spills; ~2 blocks/SM.
// Chains run 20 taps (4 channels) in fp32 then Kahan-merge (err ~1e-7 << ref
// noise). Chain start is fma(x,w,0) == mul in RN (mod -0, harmless).
__global__ __launch_bounds__(256) void k1_conv1(const float* __restrict__ x,
                                                const float* __restrict__ conv1_b) {
    __shared__ float xs[CIN][XS_W];
    __shared__ float s_part[2][GROUPS][F];
    const int b    = blockIdx.y;
    const int tile = blockIdx.x;
    const int p0   = tile * TILE_P;
    const int tid  = threadIdx.x;

    const float* xb = x + (size_t)b * CIN * T_IN;
    for (int i = tid; i < CIN*XS_W; i += 256) {
        int c = i >> 6, t = i & 63;
        int gt = p0 + t;
        if (gt > T_IN-1) gt = T_IN-1;        // clamped values never feed valid outputs
        xs[c][t] = xb[c*T_IN + gt];
    }
    __syncthreads();

    const int f    = tid & 63;
    const int g    = tid >> 6;
    const int base = g * POOL_PER_G;         // even -> 8B-aligned pair loads

    u64 acc2[PAIRS], nc2[PAIRS];             // Kahan with sign-flipped compensation
    const u64 NEG1 = pk2(-1.f, -1.f);
    const u64 Z2   = pk2(0.f, 0.f);
    {
        float bias = __ldg(&conv1_b[f]);
        u64 b2 = pk2(bias, bias);
        #pragma unroll
        for (int p = 0; p < PAIRS; p++) { acc2[p] = b2; nc2[p] = Z2; }
    }

    #pragma unroll 1
    for (int cb = 0; cb < CIN/4; cb++) {
        u64 cacc[PAIRS];
        #pragma unroll
        for (int p = 0; p < PAIRS; p++) cacc[p] = Z2;

        #pragma unroll 1
        for (int cc = 0; cc < 4; cc++) {
            const int c = cb*4 + cc;
            const float* xrow = &xs[c][base];
            u64 E[11];
            #pragma unroll
            for (int i = 0; i < 11; i++) E[i] = *(const u64*)(xrow + 2*i);
            u64 O[10];
            #pragma unroll
            for (int i = 0; i < 10; i++) {
                float lo0, hi0, lo1, hi1;
                upk2(lo0, hi0, E[i]); upk2(lo1, hi1, E[i+1]);
                O[i] = pk2(hi0, lo1);
            }
            u64 W[WIN];
            #pragma unroll
            for (int k = 0; k < WIN; k++) {
                float w = __ldg(&g_wT[(c*WIN + k)*F + f]);
                W[k] = pk2(w, w);
            }
            #pragma unroll
            for (int p = 0; p < PAIRS; p++) {
                u64 a = cacc[p];
                a = fma2(E[p],   W[0], a);
                a = fma2(O[p],   W[1], a);
                a = fma2(E[p+1], W[2], a);
                a = fma2(O[p+1], W[3], a);
                a = fma2(E[p+2], W[4], a);
                cacc[p] = a;
            }
        }
        // packed Kahan merge (RN symmetric under negation -> scalar-equivalent)
        #pragma unroll
        for (int p = 0; p < PAIRS; p++) {
            u64 y   = add2(cacc[p], nc2[p]);       //  v - c
            u64 s2  = add2(acc2[p], y);            //  s + y
            u64 ns2 = fma2(s2, NEG1, Z2);          // -s2 (exact)
            u64 d   = add2(acc2[p], ns2);          //  s - s2
            nc2[p]  = add2(d, y);                  // -((s2-s) - y)
            acc2[p] = s2;
        }
    }

    float hc[CONV_PER_G];
    #pragma unroll
    for (int p = 0; p < PAIRS; p++) {
        u64 h2 = add2(acc2[p], nc2[p]);            // acc - comp
        upk2(hc[2*p], hc[2*p+1], h2);
    }

    // maxpool(5, stride 1) thread-local; store [b][p][f] (coalesced)
    float s = 0.f, sq = 0.f;
    float* hpb = g_hp + (size_t)b * TPOOL * F;
    #pragma unroll
    for (int t = 0; t < POOL_PER_G; t++) {
        float m = hc[t];
        m = fmaxf(m, hc[t+1]); m = fmaxf(m, hc[t+2]);
        m = fmaxf(m, hc[t+3]); m = fmaxf(m, hc[t+4]);
        int p = p0 + base + t;
        if (p < TPOOL) {
            hpb[p*F + f] = m;
            s  += m;
            sq = fmaf(m, m, sq);
        }
    }
    s_part[0][g][f] = s;
    s_part[1][g][f] = sq;
    __syncthreads();
    if (g == 0) {   // deterministic fixed-order combine
        float ts = 0.f, tq = 0.f;
        #pragma unroll
        for (int gg = 0; gg < GROUPS; gg++) { ts += s_part[0][gg][f]; tq += s_part[1][gg][f]; }
        int blk = b*NTILE + tile;
        g_psum[blk*F + f] = ts;
        g_psq [blk*F + f] = tq;
    }
}

// ---------------- K2: exact-enough BN reduce -> fp32 mu and rsqrt ----------
__global__ void k2_bn(void) {
    __shared__ double red[256];
    const int f = blockIdx.x, tid = threadIdx.x;
    double s = 0.0;
    for (int i = tid; i < NBLK1; i += 256) s += (double)g_psum[i*F + f];
    red[tid] = s; __syncthreads();
    for (int st = 128; st > 0; st >>= 1) { if (tid < st) red[tid] += red[tid+st]; __syncthreads(); }
    double tot = red[0]; __syncthreads();
    double q = 0.0;
    for (int i = tid; i < NBLK1; i += 256) q += (double)g_psq[i*F + f];
    red[tid] = q; __syncthreads();
    for (int st = 128; st > 0; st >>= 1) { if (tid < st) red[tid] += red[tid+st]; __syncthreads(); }
    if (tid == 0) {
        const double cnt = (double)BATCH * TPOOL;
        double mu  = tot / cnt;
        double var = red[0] / cnt - mu*mu;
        float muf  = (float)mu;
        float varf = (float)var;                        // ref's var is an fp32 value
        float sf   = __fadd_rn(varf, 1e-5f);            // ref: var + BN_EPS in fp32
        double r   = 1.0 / sqrt((double)sf);            // correctly-rounded rsqrt
        g_muf[f] = muf;
        g_rf [f] = (float)r;
    }
}

// ---------------- K4: fp32 BN steps + conv2 (per-f chain + Kahan) -> idx ---
__global__ __launch_bounds__(256) void k4_conv2(const float* __restrict__ bn_gamma,
                                                const float* __restrict__ bn_beta,
                                                const float* __restrict__ conv2_w,
                                                const float* __restrict__ conv2_b) {
    __shared__ float  hps[132*65];       // padded stride 65 -> conflict-free
    __shared__ float  w2s[F*WIN];
    __shared__ float2 part2[2][128];
    const int b  = blockIdx.y;
    const int l0 = blockIdx.x * 128;
    const int tid = threadIdx.x;

    const float* hpb = g_hp + (size_t)b * TPOOL * F;
    for (int i = tid; i < 132*F; i += 256) {
        int p = i >> 6, f = i & 63;
        int gp = l0 + p;
        if (gp > TPOOL-1) gp = TPOOL-1;               // feeds only discarded l
        float h  = hpb[gp*F + f];
        float t1 = __fsub_rn(h,  g_muf[f]);
        float t2 = __fmul_rn(t1, g_rf[f]);
        float t3 = __fmul_rn(t2, bn_gamma[f]);
        float t4 = __fadd_rn(t3, bn_beta[f]);
        hps[p*65 + f] = t4;
    }
    for (int i = tid; i < F*WIN; i += 256) w2s[i] = conv2_w[i];
    __syncthreads();

    const int half = tid >> 7, lloc = tid & 127;
    const int f0 = half * 32;
    float vs = 0.f, vc = 0.f;
    for (int f = f0; f < f0 + 32; f++) {
        // per-f 5-tap fp32 chain (err ~1e-8), then one Kahan merge
        float a = __fmul_rn(hps[(lloc  )*65 + f], w2s[f*WIN+0]);
        a = fmaf(hps[(lloc+1)*65 + f], w2s[f*WIN+1], a);
        a = fmaf(hps[(lloc+2)*65 + f], w2s[f*WIN+2], a);
        a = fmaf(hps[(lloc+3)*65 + f], w2s[f*WIN+3], a);
        a = fmaf(hps[(lloc+4)*65 + f], w2s[f*WIN+4], a);
        float y = __fsub_rn(a, vc);
        float t = __fadd_rn(vs, y);
        vc = __fsub_rn(__fsub_rn(t, vs), y);
        vs = t;
    }
    part2[half][lloc] = make_float2(vs, vc);
    __syncthreads();
    if (half == 0) {
        int l = l0 + lloc;
        if (l < L) {
            float2 q0 = part2[0][lloc], q1 = part2[1][lloc];
            double vd = ((double)q0.x - (double)q0.y)
                      + ((double)q1.x - (double)q1.y)
                      + (double)conv2_b[0];
            float vf = (float)vd;                       // ref conv2 output is fp32
            vf = fmaxf(vf, 0.f);                        // relu (fp32, exact)
            double cd = 1.0 / (1.0 + exp(-(double)vf)); // true sigmoid of fp32 v
            float cf = (float)cd;                       // round c to fp32 like ref
            float pf = __fmul_rn(cf, 256.0f);           // exact (x2^8)
            int id = (int)ceilf(pf) - 1;
            id = min(max(id, 0), 255);
            g_idx[b*L + l] = id;
        }
    }
}

// ---------------- K5: bucket scatter (127 fast path) + tau + partial A -----
// grid (CHUNKS, BATCH), 256 threads. S in shared (AC x 260 padded).
// ~half of all l hit bucket 127 (relu zeros -> c=0.5): those accumulate in
// registers and land via one warp-reduced atomic instead of contended ATOMS.
__global__ __launch_bounds__(256) void k5_att(const float* __restrict__ emb,
                                              const float* __restrict__ W2) {
    __shared__ float S[AC*260];   // stride 260: float4-aligned, banks spread
    const int b = blockIdx.y, chunk = blockIdx.x;
    const int a0 = chunk * AC;
    const int tid = threadIdx.x;

    for (int i = tid; i < AC*260; i += 256) S[i] = 0.f;
    __syncthreads();

    float a127[AC];
    #pragma unroll
    for (int a = 0; a < AC; a++) a127[a] = 0.f;

    const int* idxb = g_idx + b*L;
    for (int l = tid; l < L; l += 256) {
        int j = idxb[l];
        const float4* w4 = (const float4*)(g_W1T + l*DA + a0);
        float4 v0 = w4[0], v1 = w4[1];
        if (j == 127) {
            a127[0] += v0.x; a127[1] += v0.y; a127[2] += v0.z; a127[3] += v0.w;
            a127[4] += v1.x; a127[5] += v1.y; a127[6] += v1.z; a127[7] += v1.w;
        } else {
            atomicAdd(&S[0*260 + j], v0.x); atomicAdd(&S[1*260 + j], v0.y);
            atomicAdd(&S[2*260 + j], v0.z); atomicAdd(&S[3*260 + j], v0.w);
            atomicAdd(&S[4*260 + j], v1.x); atomicAdd(&S[5*260 + j], v1.y);
            atomicAdd(&S[6*260 + j], v1.z); atomicAdd(&S[7*260 + j], v1.w);
        }
    }
    // warp-reduce the 127 bucket, one atomic per warp per a
    #pragma unroll
    for (int a = 0; a < AC; a++) {
        float v = a127[a];
        #pragma unroll
        for (int o = 16; o > 0; o >>= 1) v += __shfl_xor_sync(0xFFFFFFFFu, v, o);
        if ((tid & 31) == 0) atomicAdd(&S[a*260 + 127], v);
    }
    __syncthreads();

    const int d = tid;     // 256 threads = 256 d
    float tau[AC];
    #pragma unroll
    for (int a = 0; a < AC; a++) tau[a] = 0.f;
    for (int j4 = 0; j4 < 64; j4++) {
        int j = j4 * 4;
        float e0 = __ldg(&emb[(j+0)*D + d]);
        float e1 = __ldg(&emb[(j+1)*D + d]);
        float e2 = __ldg(&emb[(j+2)*D + d]);
        float e3 = __ldg(&emb[(j+3)*D + d]);
        #pragma unroll
        for (int a = 0; a < AC; a++) {
            float4 s4 = *(const float4*)&S[a*260 + j];   // warp-uniform LDS.128
            tau[a] = fmaf(s4.x, e0, tau[a]);
            tau[a] = fmaf(s4.y, e1, tau[a]);
            tau[a] = fmaf(s4.z, e2, tau[a]);
            tau[a] = fmaf(s4.w, e3, tau[a]);
        }
    }
    float Ad = 0.f;
    #pragma unroll
    for (int a = 0; a < AC; a++)
        Ad = fmaf(__ldg(&W2[a0 + a]), tanhf(tau[a]), Ad);
    g_Apart[(chunk*BATCH + b)*D + d] = Ad;
}

// ---------------- K6: A combine + P = E@A + scores -------------------------
__global__ void k6_scoresP(const float* __restrict__ emb,
                           const float* __restrict__ lin_w,
                           const float* __restrict__ lin_b,
                           float* __restrict__ out) {
    __shared__ float As[D];
    const int b = blockIdx.x, tid = threadIdx.x;   // 256 threads
    float A = 0.f;
    #pragma unroll
    for (int ch = 0; ch < CHUNKS; ch++)
        A += g_Apart[(ch*BATCH + b)*D + tid];
    As[tid] = A;
    __syncthreads();

    {
        const int j = tid;
        float acc = 0.f;
        for (int d4 = 0; d4 < 64; d4++) {
            float4 e = __ldg((const float4*)&emb[j*D + d4*4]);
            float4 a = *(const float4*)&As[d4*4];
            acc = fmaf(e.x, a.x, acc); acc = fmaf(e.y, a.y, acc);
            acc = fmaf(e.z, a.z, acc); acc = fmaf(e.w, a.w, acc);
        }
        g_P[b*D + j] = acc;
    }
    if (tid < SECTORS) {
        float sa = 0.f;
        const float* lw = lin_w + tid*D;
        for (int dd = 0; dd < D; dd++) sa = fmaf(As[dd], __ldg(&lw[dd]), sa);
        out[ATT_SIZE + b*SECTORS + tid] = sa + lin_b[tid];
    }
}

// ---------------- K7: att = softmax over l of P[b, idx[b,l]] ---------------
__global__ __launch_bounds__(256) void k7_softmax(float* __restrict__ out) {
    __shared__ float Ps[D];
    __shared__ float red[256];
    const int b = blockIdx.x, tid = threadIdx.x;
    Ps[tid] = g_P[b*D + tid];
    __syncthreads();

    const int* idxb = g_idx + b*L;
    float z[8];
    float m = -3.0e38f;
    #pragma unroll
    for (int k = 0; k < 8; k++) {
        int l = tid + k*256;
        if (l < L) { z[k] = Ps[idxb[l]]; m = fmaxf(m, z[k]); }
        else z[k] = -3.0e38f;
    }
    red[tid] = m; __syncthreads();
    for (int st = 128; st > 0; st >>= 1) { if (tid < st) red[tid] = fmaxf(red[tid], red[tid+st]); __syncthreads(); }
    const float M = red[0]; __syncthreads();

    float s = 0.f;
    float ez[8];
    #pragma unroll
    for (int k = 0; k < 8; k++) {
        int l = tid + k*256;
        if (l < L) { ez[k] = expf(z[k] - M); s += ez[k]; }
        else ez[k] = 0.f;
    }
    red[tid] = s; __syncthreads();
    for (int st = 128; st > 0; st >>= 1) { if (tid < st) red[tid] += red[tid+st]; __syncthreads(); }
    const float inv = 1.f / red[0];
    #pragma unroll
    for (int k = 0; k < 8; k++) {
        int l = tid + k*256;
        if (l < L) out[b*L + l] = ez[k] * inv;
    }
}

// ---------------- launcher -------------------------------------------------
extern "C" void kernel_launch(void* const* d_in, const int* in_sizes, int n_in,
                              void* d_out, int out_size) {
    const float* x        = (const float*)d_in[0];
    const float* conv1_w  = (const float*)d_in[1];
    const float* conv1_b  = (const float*)d_in[2];
    const float* bn_gamma = (const float*)d_in[3];
    const float* bn_beta  = (const float*)d_in[4];
    const float* conv2_w  = (const float*)d_in[5];
    const float* conv2_b  = (const float*)d_in[6];
    const float* emb      = (const float*)d_in[7];
    const float* W1       = (const float*)d_in[8];
    const float* W2       = (const float*)d_in[9];
    const float* lin_w    = (const float*)d_in[10];
    const float* lin_b    = (const float*)d_in[11];
    float* out = (float*)d_out;

    k0_prep<<<512, 256>>>(conv1_w, W1);
    dim3 g1(NTILE, BATCH);
    k1_conv1<<<g1, 256>>>(x, conv1_b);
    k2_bn<<<F, 256>>>();
    dim3 g4(16, BATCH);
    k4_conv2<<<g4, 256>>>(bn_gamma, bn_beta, conv2_w, conv2_b);
    dim3 g5(CHUNKS, BATCH);
    k5_att<<<g5, 256>>>(emb, W2);
    k6_scoresP<<<BATCH, 256>>>(emb, lin_w, lin_b, out);
    k7_softmax<<<BATCH, 256>>>(out);
}